// round 15
// baseline (speedup 1.0000x reference)
#include <cuda_runtime.h>
#include <cuda_bf16.h>
#include <mma.h>
#include <math.h>

using namespace nvcuda;

#define Bc 256
#define FEWc 5
#define Mc 200
#define Dc 100
#define Hc 450
#define NSYMc 70000
#define HP 464
#define NP 1856
#define K0P 640
#define K1P 2752
#define NPAD 1920
#define XWS 3840

__device__ __align__(16) float d_P[(NSYMc + 1) * 200];
__device__ __align__(16) float d_W2[200 * 100];
__device__ __align__(16) __nv_bfloat16 d_Xb[1280 * K0P];
__device__ __align__(16) __nv_bfloat16 d_y0b[1280 * K1P];
__device__ __align__(16) __nv_bfloat16 d_Wih0b[2 * NPAD * K0P];
__device__ __align__(16) __nv_bfloat16 d_Wih1b[2 * NPAD * K1P];
__device__ __align__(16) float d_XW0[1280 * XWS];
__device__ __align__(16) float d_XW1[1280 * XWS];
__device__ __align__(16) float d_y1[FEWc * Bc * 900];
__device__ __align__(16) float d_hA[2 * Bc * HP];
__device__ __align__(16) float d_hB[2 * Bc * HP];
__device__ __align__(16) float d_cst[2 * Bc * Hc];
__device__ __align__(16) float d_Whh0i[2 * NP * HP];
__device__ __align__(16) float d_Whh1i[2 * NP * HP];
__device__ __align__(16) float d_bs0[2 * 1800];
__device__ __align__(16) float d_bs1[2 * 1800];
__device__ __align__(16) float d_finals[4 * Bc * Hc];
__device__ __align__(16) float d_rel[Bc * Dc];
__device__ __align__(16) float d_relq[Bc * Dc];
__device__ __align__(16) float d_normq[Bc * Dc];

__device__ __forceinline__ float sigm(float x) { return 1.0f / (1.0f + expf(-x)); }
__device__ __forceinline__ float warpred(float v) {
    for (int o = 16; o > 0; o >>= 1) v += __shfl_xor_sync(0xffffffff, v, o);
    return v;
}
__device__ __forceinline__ void split_bf(float x, __nv_bfloat16& hi, __nv_bfloat16& lo) {
    hi = __float2bfloat16(x);
    lo = __float2bfloat16(x - __bfloat162float(hi));
}

#define CP16(smaddr, gptr) \
    asm volatile("cp.async.cg.shared.global [%0], [%1], 16;\n" :: "r"(smaddr), "l"(gptr))
#define CP_COMMIT() asm volatile("cp.async.commit_group;\n" ::)
#define CP_WAIT0()  asm volatile("cp.async.wait_group 0;\n" ::)
#define CP_WAIT1()  asm volatile("cp.async.wait_group 1;\n" ::)

// ====== bf16 tensor-core NT GEMM, BK=64, 3-stage cp.async, 1 sync/tile =====
// C[m][n] = sum_k A[m][k]*B[n][k]. BM=BN=128, BK=64, 8 warps (2x4), warp
// tile 64x32. All dims padded (K mult of 64); no guards. Smem 110.6KB dyn.
__global__ __launch_bounds__(256) void hgemm_nt(
    int T,
    const __nv_bfloat16* __restrict__ A, int lda, long long sA,
    const __nv_bfloat16* __restrict__ Bm, int ldb, long long sB,
    float* __restrict__ C, int ldc, long long sC)
{
    constexpr int LDS_ = 72;               // 144B row stride, conflict-free
    constexpr int STAGE = 128 * LDS_;      // halfs per matrix per stage
    extern __shared__ __nv_bfloat16 sm[];  // 3 * 2 * STAGE halfs = 110592B
    A  += (long long)blockIdx.z * sA;
    Bm += (long long)blockIdx.z * sB;
    C  += (long long)blockIdx.z * sC;
    const int tid = threadIdx.x;
    const int warp = tid >> 5;
    const int warpM = warp >> 2, warpN = warp & 3;
    const int m0 = blockIdx.y * 128, n0 = blockIdx.x * 128;

    auto issue = [&](int t, int buf) {
        const __nv_bfloat16* Ak = A + (long long)m0 * lda + t * 64;
        const __nv_bfloat16* Bk = Bm + (long long)n0 * ldb + t * 64;
        __nv_bfloat16* sa = sm + buf * 2 * STAGE;
        __nv_bfloat16* sb = sa + STAGE;
#pragma unroll
        for (int v = 0; v < 4; v++) {
            int idx = tid + v * 256, r = idx >> 3, cs = (idx & 7) * 8;
            CP16((unsigned)__cvta_generic_to_shared(sa + r * LDS_ + cs), Ak + (long long)r * lda + cs);
            CP16((unsigned)__cvta_generic_to_shared(sb + r * LDS_ + cs), Bk + (long long)r * ldb + cs);
        }
        CP_COMMIT();
    };

    wmma::fragment<wmma::accumulator, 16, 16, 16, float> acc[4][2];
#pragma unroll
    for (int i = 0; i < 4; i++)
#pragma unroll
        for (int j = 0; j < 2; j++) wmma::fill_fragment(acc[i][j], 0.0f);

    issue(0, 0);
    if (T > 1) issue(1, 1);
    int buf = 0;
    for (int t = 0; t < T; t++) {
        if (t + 1 < T) CP_WAIT1();   // stage t done; stage t+1 may be in flight
        else           CP_WAIT0();   // final stage is the newest: drain fully
        __syncthreads();
        if (t + 2 < T) {
            int nb = buf + 2; if (nb >= 3) nb -= 3;
            issue(t + 2, nb);        // overwrites stage (t-1)'s buffer — safe
        }
        const __nv_bfloat16* sa = sm + buf * 2 * STAGE;
        const __nv_bfloat16* sb = sa + STAGE;
#pragma unroll
        for (int ks = 0; ks < 4; ks++) {
            wmma::fragment<wmma::matrix_b, 16, 16, 16, __nv_bfloat16, wmma::col_major> bfr[2];
#pragma unroll
            for (int j = 0; j < 2; j++)
                wmma::load_matrix_sync(bfr[j], sb + (warpN * 32 + j * 16) * LDS_ + ks * 16, LDS_);
#pragma unroll
            for (int i = 0; i < 4; i++) {
                wmma::fragment<wmma::matrix_a, 16, 16, 16, __nv_bfloat16, wmma::row_major> afr;
                wmma::load_matrix_sync(afr, sa + (warpM * 64 + i * 16) * LDS_ + ks * 16, LDS_);
#pragma unroll
                for (int j = 0; j < 2; j++)
                    wmma::mma_sync(acc[i][j], afr, bfr[j], acc[i][j]);
            }
        }
        if (++buf == 3) buf = 0;
    }
#pragma unroll
    for (int i = 0; i < 4; i++)
#pragma unroll
        for (int j = 0; j < 2; j++)
            wmma::store_matrix_sync(
                C + (long long)(m0 + warpM * 64 + i * 16) * ldc + n0 + warpN * 32 + j * 16,
                acc[i][j], ldc, wmma::mem_row_major);
}

// ====== fp32 NT SGEMM (single-buffer, proven) — used for P only ============
template <int BM, int BN, int BK, int TM, int TN, bool GUARD>
__global__ __launch_bounds__(256, 2) void sgemm_nt(
    int M, int N, int K, int T,
    const float* __restrict__ A, int lda, long long sA,
    const float* __restrict__ Bm, int ldb, long long sB,
    float* __restrict__ C, int ldc, long long sC)
{
    constexpr int TX = BN / TN, TY = BM / TM;
    static_assert(TX * TY == 256, "");
    constexpr int KV = BK / 4;
    constexpr int NVA = BM * BK / 1024, NVB = BN * BK / 1024;
    __shared__ float As[BK][BM + 4];
    __shared__ float Bs[BK][BN + 4];
    A  += (long long)blockIdx.z * sA;
    Bm += (long long)blockIdx.z * sB;
    C  += (long long)blockIdx.z * sC;
    const int tid = threadIdx.x, tx = tid % TX, ty = tid / TX;
    const int m0 = blockIdx.y * BM, n0 = blockIdx.x * BN;
    const float4 z4 = make_float4(0.f, 0.f, 0.f, 0.f);

    float4 aR[NVA], bR[NVB];
#pragma unroll
    for (int v = 0; v < NVA; v++) {
        int idx = tid + v * 256, r = idx / KV, kv = idx % KV;
        int gm = m0 + r, gk = kv * 4;
        aR[v] = (!GUARD || (gm < M && gk < K)) ? *(const float4*)(A + (long long)gm * lda + gk) : z4;
    }
#pragma unroll
    for (int v = 0; v < NVB; v++) {
        int idx = tid + v * 256, r = idx / KV, kv = idx % KV;
        int gn = n0 + r, gk = kv * 4;
        bR[v] = (!GUARD || (gn < N && gk < K)) ? *(const float4*)(Bm + (long long)gn * ldb + gk) : z4;
    }

    unsigned long long acc2[TM][TN / 2];
#pragma unroll
    for (int i = 0; i < TM; i++)
#pragma unroll
        for (int j = 0; j < TN / 2; j++) acc2[i][j] = 0ull;

    for (int t = 0; t < T; t++) {
#pragma unroll
        for (int v = 0; v < NVA; v++) {
            int idx = tid + v * 256, r = idx / KV, kv = idx % KV;
            As[kv * 4 + 0][r] = aR[v].x; As[kv * 4 + 1][r] = aR[v].y;
            As[kv * 4 + 2][r] = aR[v].z; As[kv * 4 + 3][r] = aR[v].w;
        }
#pragma unroll
        for (int v = 0; v < NVB; v++) {
            int idx = tid + v * 256, r = idx / KV, kv = idx % KV;
            Bs[kv * 4 + 0][r] = bR[v].x; Bs[kv * 4 + 1][r] = bR[v].y;
            Bs[kv * 4 + 2][r] = bR[v].z; Bs[kv * 4 + 3][r] = bR[v].w;
        }
        __syncthreads();
        if (t + 1 < T) {
            int k0 = (t + 1) * BK;
#pragma unroll
            for (int v = 0; v < NVA; v++) {
                int idx = tid + v * 256, r = idx / KV, kv = idx % KV;
                int gm = m0 + r, gk = k0 + kv * 4;
                aR[v] = (!GUARD || (gm < M && gk < K)) ? *(const float4*)(A + (long long)gm * lda + gk) : z4;
            }
#pragma unroll
            for (int v = 0; v < NVB; v++) {
                int idx = tid + v * 256, r = idx / KV, kv = idx % KV;
                int gn = n0 + r, gk = k0 + kv * 4;
                bR[v] = (!GUARD || (gn < N && gk < K)) ? *(const float4*)(Bm + (long long)gn * ldb + gk) : z4;
            }
        }
#pragma unroll
        for (int kk = 0; kk < BK; kk++) {
            float4 raV[TM / 4];
#pragma unroll
            for (int i = 0; i < TM / 4; i++)
                raV[i] = *(const float4*)&As[kk][ty * TM + 4 * i];
            const float* ra = (const float*)raV;
            float4 rbV[TN / 4];
#pragma unroll
            for (int j = 0; j < TN / 4; j++)
                rbV[j] = *(const float4*)&Bs[kk][tx * TN + 4 * j];
            const unsigned long long* rb = (const unsigned long long*)rbV;
#pragma unroll
            for (int i = 0; i < TM; i++) {
                unsigned long long a2;
                unsigned au = __float_as_uint(ra[i]);
                asm("mov.b64 %0,{%1,%1};" : "=l"(a2) : "r"(au));
#pragma unroll
                for (int j = 0; j < TN / 2; j++)
                    asm("fma.rn.f32x2 %0,%1,%2,%3;"
                        : "=l"(acc2[i][j]) : "l"(a2), "l"(rb[j]), "l"(acc2[i][j]));
            }
        }
        __syncthreads();
    }
#pragma unroll
    for (int i = 0; i < TM; i++) {
        int m = m0 + ty * TM + i;
        if (m >= M) continue;
#pragma unroll
        for (int j = 0; j < TN / 2; j++) {
            union { unsigned long long u; float f[2]; } cv;
            cv.u = acc2[i][j];
            int n = n0 + tx * TN + 2 * j;
            if (n + 1 < N) *(float2*)(C + (long long)m * ldc + n) = make_float2(cv.f[0], cv.f[1]);
            else if (n < N) C[(long long)m * ldc + n] = cv.f[0];
        }
    }
}

// ====== fused recurrent GEMM + LSTM cell (fp32, proven) ====================
__global__ __launch_bounds__(256) void lstm_rec(
    const float* __restrict__ h_in, const float* __restrict__ Whh,
    const float* __restrict__ XW, const float* __restrict__ bs,
    float* __restrict__ h_out, float* __restrict__ c,
    float* __restrict__ y, __nv_bfloat16* __restrict__ ybf,
    int step, int finalsBase)
{
    constexpr int BK = 16, KV = 4;
    __shared__ float As[BK][68];
    __shared__ float Bs[BK][68];
    const int dir = blockIdx.z;
    const float* A  = h_in + (long long)dir * Bc * HP;
    const float* Bm = Whh + (long long)dir * NP * HP;
    const int tid = threadIdx.x, tx = tid % 16, ty = tid / 16;
    const int m0 = blockIdx.y * 64, n0 = blockIdx.x * 64;
    const int T = HP / BK;
    const int r = tid / KV, kv = tid % KV;

    float4 aR = *(const float4*)(A + (long long)(m0 + r) * HP + kv * 4);
    float4 bR = *(const float4*)(Bm + (long long)(n0 + r) * HP + kv * 4);

    unsigned long long acc2[4][2];
#pragma unroll
    for (int i = 0; i < 4; i++) { acc2[i][0] = 0ull; acc2[i][1] = 0ull; }

    for (int t = 0; t < T; t++) {
        As[kv * 4 + 0][r] = aR.x; As[kv * 4 + 1][r] = aR.y;
        As[kv * 4 + 2][r] = aR.z; As[kv * 4 + 3][r] = aR.w;
        Bs[kv * 4 + 0][r] = bR.x; Bs[kv * 4 + 1][r] = bR.y;
        Bs[kv * 4 + 2][r] = bR.z; Bs[kv * 4 + 3][r] = bR.w;
        __syncthreads();
        if (t + 1 < T) {
            int gk = (t + 1) * BK + kv * 4;
            aR = *(const float4*)(A + (long long)(m0 + r) * HP + gk);
            bR = *(const float4*)(Bm + (long long)(n0 + r) * HP + gk);
        }
#pragma unroll
        for (int kk = 0; kk < BK; kk++) {
            float4 raV = *(const float4*)&As[kk][ty * 4];
            const float* ra = (const float*)&raV;
            float4 rbV = *(const float4*)&Bs[kk][tx * 4];
            const unsigned long long* rb = (const unsigned long long*)&rbV;
#pragma unroll
            for (int i = 0; i < 4; i++) {
                unsigned long long a2;
                unsigned au = __float_as_uint(ra[i]);
                asm("mov.b64 %0,{%1,%1};" : "=l"(a2) : "r"(au));
                asm("fma.rn.f32x2 %0,%1,%2,%3;" : "=l"(acc2[i][0]) : "l"(a2), "l"(rb[0]), "l"(acc2[i][0]));
                asm("fma.rn.f32x2 %0,%1,%2,%3;" : "=l"(acc2[i][1]) : "l"(a2), "l"(rb[1]), "l"(acc2[i][1]));
            }
        }
        __syncthreads();
    }

    const int jj = (n0 >> 2) + tx;
    if (jj >= Hc) return;
    const int tstep = dir ? (4 - step) : step;
    const float4 bsv = *(const float4*)(bs + dir * 1800 + 4 * jj);
#pragma unroll
    for (int i = 0; i < 4; i++) {
        int b = m0 + ty * 4 + i;
        union { unsigned long long u; float f[2]; } c0, c1;
        c0.u = acc2[i][0]; c1.u = acc2[i][1];
        const float4 xwv = *(const float4*)(XW + ((long long)(tstep * Bc + b)) * XWS + dir * NPAD + 4 * jj);
        float gi = c0.f[0] + xwv.x + bsv.x;
        float gf = c0.f[1] + xwv.y + bsv.y;
        float gg = c1.f[0] + xwv.z + bsv.z;
        float go = c1.f[1] + xwv.w + bsv.w;
        int ci = (dir * Bc + b) * Hc + jj;
        float cp = c[ci];
        float cn = sigm(gf) * cp + sigm(gi) * tanhf(gg);
        float hn = sigm(go) * tanhf(cn);
        c[ci] = cn;
        h_out[(dir * Bc + b) * HP + jj] = hn;
        if (ybf) {
            __nv_bfloat16 hi, lo;
            split_bf(hn, hi, lo);
            long long base = ((long long)(tstep * Bc + b)) * K1P + 3 * (dir * Hc + jj);
            ybf[base] = hi; ybf[base + 1] = lo; ybf[base + 2] = hi;
        } else {
            y[((long long)(tstep * Bc + b)) * 900 + dir * Hc + jj] = hn;
        }
        if (step == 4) d_finals[((long long)(finalsBase + dir) * Bc + b) * Hc + jj] = hn;
    }
}

// ============ step 0 (no recurrent term) ===================================
__global__ void lstm_step0(const float* __restrict__ XW, const float* __restrict__ bs,
                           float* __restrict__ h_out, float* __restrict__ c,
                           float* __restrict__ y, __nv_bfloat16* __restrict__ ybf)
{
    int idx = blockIdx.x * blockDim.x + threadIdx.x;
    if (idx >= 2 * Bc * Hc) return;
    int dir = idx / (Bc * Hc);
    int r = idx - dir * Bc * Hc;
    int b = r / Hc, j = r - (r / Hc) * Hc;
    int t = dir ? 4 : 0;
    const float4 xwv = *(const float4*)(XW + ((long long)(t * Bc + b)) * XWS + dir * NPAD + 4 * j);
    const float4 bsv = *(const float4*)(bs + dir * 1800 + 4 * j);
    float gi = xwv.x + bsv.x, gg = xwv.z + bsv.z, go = xwv.w + bsv.w;
    float cn = sigm(gi) * tanhf(gg);
    float hn = sigm(go) * tanhf(cn);
    c[(dir * Bc + b) * Hc + j] = cn;
    h_out[(dir * Bc + b) * HP + j] = hn;
    if (ybf) {
        __nv_bfloat16 hi, lo;
        split_bf(hn, hi, lo);
        long long base = ((long long)(t * Bc + b)) * K1P + 3 * (dir * Hc + j);
        ybf[base] = hi; ybf[base + 1] = lo; ybf[base + 2] = hi;
    } else {
        y[((long long)(t * Bc + b)) * 900 + dir * Hc + j] = hn;
    }
}

// ============ prep kernels =================================================
__global__ void prep_small(const float* __restrict__ gcn_w,
                           const float* __restrict__ bih0, const float* __restrict__ bhh0,
                           const float* __restrict__ bih1, const float* __restrict__ bhh1)
{
    int i = blockIdx.x * blockDim.x + threadIdx.x;
    const int HZ = 2 * Bc * HP;
    if (i < 20000) {
        int op = i / 100, k = i - op * 100;
        d_W2[op * 100 + k] = gcn_w[(op % 100) * 200 + (op / 100) * 100 + k];
    } else if (i < 23600) {
        int r = i - 20000, dir = r / 1800, q = r - dir * 1800;
        int j = q >> 2, g = q & 3, s = dir * 1800 + g * 450 + j;
        d_bs0[dir * 1800 + q] = bih0[s] + bhh0[s];
    } else if (i < 27200) {
        int r = i - 23600, dir = r / 1800, q = r - dir * 1800;
        int j = q >> 2, g = q & 3, s = dir * 1800 + g * 450 + j;
        d_bs1[dir * 1800 + q] = bih1[s] + bhh1[s];
    } else if (i < 27200 + HZ) {
        d_hA[i - 27200] = 0.0f;
    } else if (i < 27200 + 2 * HZ) {
        d_hB[i - 27200 - HZ] = 0.0f;
    } else if (i < 27200 + 2 * HZ + 1280 * 40) {
        int i2 = i - 27200 - 2 * HZ;
        int row = i2 / 40, cc = 600 + (i2 % 40);
        d_Xb[(long long)row * K0P + cc] = __float2bfloat16(0.0f);
    } else if (i < 27200 + 2 * HZ + 1280 * 40 + 1280 * 52) {
        int i2 = i - 27200 - 2 * HZ - 1280 * 40;
        int row = i2 / 52, cc = 2700 + (i2 % 52);
        d_y0b[(long long)row * K1P + cc] = __float2bfloat16(0.0f);
    }
}

__global__ void prep_ihb(const float* __restrict__ Wih0, const float* __restrict__ Wih1)
{
    const int L0SZ = 2 * NPAD * K0P;
    int i = blockIdx.x * blockDim.x + threadIdx.x;
    if (i < L0SZ) {
        int dir = i / (NPAD * K0P), rem = i - dir * (NPAD * K0P);
        int q = rem / K0P, cc = rem - q * K0P;
        __nv_bfloat16 outv = __float2bfloat16(0.0f);
        if (q < 1800 && cc < 600) {
            int k = cc / 3, p = cc - 3 * k;
            int j = q >> 2, g = q & 3;
            float w = Wih0[dir * 360000 + (g * 450 + j) * 200 + k];
            __nv_bfloat16 hi, lo;
            split_bf(w, hi, lo);
            outv = (p == 2) ? lo : hi;
        }
        d_Wih0b[i] = outv;
    } else if (i < L0SZ + 2 * NPAD * K1P) {
        int i2 = i - L0SZ;
        int dir = i2 / (NPAD * K1P), rem = i2 - dir * (NPAD * K1P);
        int q = rem / K1P, cc = rem - q * K1P;
        __nv_bfloat16 outv = __float2bfloat16(0.0f);
        if (q < 1800 && cc < 2700) {
            int k = cc / 3, p = cc - 3 * k;
            int j = q >> 2, g = q & 3;
            float w = Wih1[dir * 1620000 + (g * 450 + j) * 900 + k];
            __nv_bfloat16 hi, lo;
            split_bf(w, hi, lo);
            outv = (p == 2) ? lo : hi;
        }
        d_Wih1b[i2] = outv;
    }
}

__global__ void prep_hh(const float* __restrict__ Whh0, const float* __restrict__ Whh1)
{
    int i = blockIdx.x * blockDim.x + threadIdx.x;
    const int PER = 2 * NP * HP;
    if (i >= 2 * PER) return;
    int layer = i / PER, i2 = i - layer * PER;
    int dir = i2 / (NP * HP), rem = i2 - dir * (NP * HP);
    int r = rem / HP, k = rem - r * HP;
    float v = 0.0f;
    if (r < 1800 && k < 450) {
        int j = r >> 2, g = r & 3;
        const float* src = layer ? Whh1 : Whh0;
        v = src[dir * 810000 + (g * 450 + j) * 450 + k];
    }
    (layer ? d_Whh1i : d_Whh0i)[i2] = v;
}

// ============ neighbor encoder (1 block per row) ===========================
__global__ __launch_bounds__(256) void encoder_kernel(
    const int* __restrict__ lc, const int* __restrict__ rc,
    const float* __restrict__ emb,
    const float* __restrict__ gcn_wb, const float* __restrict__ gcn_b,
    const float* __restrict__ attn_w, const float* __restrict__ attn_wb,
    const float* __restrict__ gate_w, const float* __restrict__ gate_wb,
    const float* __restrict__ gate_b)
{
    extern __shared__ __align__(16) float outbuf[];
    __shared__ float logits[Mc], wts[Mc], bias[Dc], aw[Dc], gw[Dc], oattn[Dc], red[256], gsc;
    const int n = blockIdx.x;
    const int f = n / (2 * Bc);
    const int rem = n - f * 2 * Bc;
    const int s = rem / Bc, bb = rem - (rem / Bc) * Bc;
    const int* conn = (s == 0 ? lc : rc) + ((long long)(f * Bc + bb) * Mc) * 3;
    const int tid = threadIdx.x;
    if (tid < Dc) { bias[tid] = gcn_wb[tid] + gcn_b[tid]; aw[tid] = attn_w[tid]; gw[tid] = gate_w[tid]; }
    __syncthreads();
    const float awb = attn_wb[0];

    for (int m = tid; m < Mc; m += 256) {
        int i1 = conn[m * 3 + 1], i2 = conn[m * 3 + 2];
        const float4* p1 = (const float4*)(d_P + (long long)i1 * 200);
        const float4* p2 = (const float4*)(d_P + (long long)i2 * 200 + 100);
        float4* orow = (float4*)(outbuf + m * Dc);
        float lg = 0.0f;
#pragma unroll 25
        for (int q = 0; q < 25; q++) {
            float4 a = p1[q], b4 = p2[q];
            float v0 = a.x + b4.x + bias[4 * q + 0];
            float v1 = a.y + b4.y + bias[4 * q + 1];
            float v2 = a.z + b4.z + bias[4 * q + 2];
            float v3 = a.w + b4.w + bias[4 * q + 3];
            v0 = v0 >= 0.f ? v0 : 0.01f * v0;
            v1 = v1 >= 0.f ? v1 : 0.01f * v1;
            v2 = v2 >= 0.f ? v2 : 0.01f * v2;
            v3 = v3 >= 0.f ? v3 : 0.01f * v3;
            float4 o; o.x = v0; o.y = v1; o.z = v2; o.w = v3;
            orow[q] = o;
            lg += v0 * aw[4 * q] + v1 * aw[4 * q + 1] + v2 * aw[4 * q + 2] + v3 * aw[4 * q + 3];
        }
        logits[m] = lg + awb;
    }
    __syncthreads();

    float lm = -1e30f;
    for (int m = tid; m < Mc; m += 256) lm = fmaxf(lm, logits[m]);
    red[tid] = lm; __syncthreads();
    for (int st = 128; st > 0; st >>= 1) { if (tid < st) red[tid] = fmaxf(red[tid], red[tid + st]); __syncthreads(); }
    float mx = red[0]; __syncthreads();
    float ls = 0.0f;
    for (int m = tid; m < Mc; m += 256) { float e = expf(logits[m] - mx); wts[m] = e; ls += e; }
    red[tid] = ls; __syncthreads();
    for (int st = 128; st > 0; st >>= 1) { if (tid < st) red[tid] += red[tid + st]; __syncthreads(); }
    float inv = 1.0f / red[0]; __syncthreads();
    for (int m = tid; m < Mc; m += 256) wts[m] *= inv;
    __syncthreads();

    for (int o = tid; o < Dc; o += 256) {
        float acc = 0.0f;
        for (int m = 0; m < Mc; m++) acc += outbuf[m * Dc + o] * wts[m];
        oattn[o] = acc;
    }
    __syncthreads();

    float gd = 0.0f;
    for (int o = tid; o < Dc; o += 256) gd += oattn[o] * gw[o];
    red[tid] = gd; __syncthreads();
    for (int st = 128; st > 0; st >>= 1) { if (tid < st) red[tid] += red[tid + st]; __syncthreads(); }
    if (tid == 0) gsc = sigm(red[0] + gate_wb[0] + gate_b[0]);
    __syncthreads();
    float g = gsc;
    int self_idx = conn[0];
    const float* se = emb + (long long)self_idx * Dc;
    for (int o = tid; o < Dc; o += 256) {
        float v = oattn[o] * g + se[o] * (1.0f - g);
        __nv_bfloat16 hi, lo;
        split_bf(v, hi, lo);
        long long base = ((long long)(f * Bc + bb)) * K0P + 3 * (s * Dc + o);
        d_Xb[base] = hi; d_Xb[base + 1] = lo; d_Xb[base + 2] = hi;
    }
}

// ============ attention over LSTM output + rel projection ==================
__global__ __launch_bounds__(256) void attn_kernel(const float* __restrict__ out_w,
                                                   const float* __restrict__ out_b)
{
    __shared__ float O[FEWc * 900];
    __shared__ float Hs[1800], ctx[1800], lg[10], awt[10];
    const int b = blockIdx.x, tid = threadIdx.x;
    for (int i = tid; i < FEWc * 900; i += 256) {
        int t = i / 900, h2 = i - t * 900;
        O[i] = d_y1[((long long)t * Bc + b) * 900 + h2];
    }
    for (int i = tid; i < 1800; i += 256) Hs[i] = d_finals[(long long)b * 1800 + i];
    if (tid < 10) lg[tid] = 0.0f;
    __syncthreads();

    float part[10];
#pragma unroll
    for (int q = 0; q < 10; q++) part[q] = 0.0f;
    for (int h2 = tid; h2 < 900; h2 += 256) {
        float hl0 = Hs[2 * h2], hl1 = Hs[2 * h2 + 1];
#pragma unroll
        for (int t = 0; t < 5; t++) {
            float ov = O[t * 900 + h2];
            part[2 * t]     += ov * hl0;
            part[2 * t + 1] += ov * hl1;
        }
    }
#pragma unroll
    for (int q = 0; q < 10; q++) {
        float v = warpred(part[q]);
        if ((tid & 31) == 0) atomicAdd(&lg[q], v);
    }
    __syncthreads();
    if (tid < 2) {
        int l = tid;
        float mxv = -1e30f;
        for (int t = 0; t < 5; t++) mxv = fmaxf(mxv, lg[t * 2 + l]);
        float sm = 0.0f, e[5];
        for (int t = 0; t < 5; t++) { e[t] = expf(lg[t * 2 + l] - mxv); sm += e[t]; }
        for (int t = 0; t < 5; t++) awt[t * 2 + l] = e[t] / sm;
    }
    __syncthreads();
    for (int i = tid; i < 1800; i += 256) {
        int h2 = i >> 1, l = i & 1;
        float acc = 0.0f;
#pragma unroll
        for (int t = 0; t < 5; t++) acc += O[t * 900 + h2] * awt[t * 2 + l];
        ctx[i] = acc;
    }
    __syncthreads();
    int w = tid >> 5, lane = tid & 31;
    for (int o = w; o < Dc; o += 8) {
        float acc = 0.0f;
        for (int k = lane; k < 1800; k += 32) acc += ctx[k] * out_w[(long long)o * 1800 + k];
        acc = warpred(acc);
        if (lane == 0) d_rel[(long long)b * Dc + o] = acc + out_b[o];
    }
}

// ============ meta gradient ================================================
__global__ void meta_kernel(const float* __restrict__ support, const float* __restrict__ sneg,
                            const float* __restrict__ normv)
{
    int b = blockIdx.x, lane = threadIdx.x;
    float r4[4], n4[4], g4[4] = {0, 0, 0, 0};
#pragma unroll
    for (int i = 0; i < 4; i++) {
        int o = lane + 32 * i;
        r4[i] = (o < Dc) ? d_rel[b * Dc + o] : 0.0f;
        n4[i] = (o < Dc) ? normv[(long long)b * Dc + o] : 0.0f;
    }
    for (int k = 0; k < 5; k++) {
        const float* hp = support + ((long long)(b * 5 + k) * 2) * Dc;
        const float* tp = hp + Dc;
        const float* hn = sneg + ((long long)(b * 5 + k) * 2) * Dc;
        const float* tn = hn + Dc;
        float up[4], un[4], ap = 0.0f, an = 0.0f;
#pragma unroll
        for (int i = 0; i < 4; i++) {
            int o = lane + 32 * i;
            up[i] = (o < Dc) ? hp[o] - tp[o] : 0.0f;
            un[i] = (o < Dc) ? hn[o] - tn[o] : 0.0f;
            ap += up[i] * n4[i];
            an += un[i] * n4[i];
        }
        ap = warpred(ap); an = warpred(an);
        float dp4[4], dn4[4], sp = 0.0f, sn = 0.0f;
#pragma unroll
        for (int i = 0; i < 4; i++) {
            dp4[i] = up[i] + r4[i] - ap * n4[i];
            dn4[i] = un[i] + r4[i] - an * n4[i];
            sp += dp4[i] * dp4[i];
            sn += dn4[i] * dn4[i];
        }
        sp = warpred(sp); sn = warpred(sn);
        float Dp = sqrtf(sp), Dn = sqrtf(sn);
        if (1.0f + Dp - Dn > 0.0f) {
            float ip = 1.0f / Dp, inn = 1.0f / Dn;
#pragma unroll
            for (int i = 0; i < 4; i++) g4[i] += dp4[i] * ip - dn4[i] * inn;
        }
    }
#pragma unroll
    for (int i = 0; i < 4; i++) {
        int o = lane + 32 * i;
        if (o < Dc) {
            float g = g4[i] * (1.0f / 1280.0f);
            d_relq[b * Dc + o]  = r4[i] - 5.0f * g;
            d_normq[b * Dc + o] = n4[i] - 5.0f * g;
        }
    }
}

// ============ final scoring ================================================
__global__ __launch_bounds__(256) void score_kernel(const float* __restrict__ query,
                                                    const float* __restrict__ negative,
                                                    float* __restrict__ out)
{
    __shared__ float rq[Dc], nq[Dc];
    int b = blockIdx.y, tid = threadIdx.x;
    if (tid < Dc) { rq[tid] = d_relq[b * Dc + tid]; nq[tid] = d_normq[b * Dc + tid]; }
    __syncthreads();
    int w = tid >> 5, lane = tid & 31;
    int q = blockIdx.x * 8 + w;
    if (q >= 522) return;
    const float* hp;
    if (q < 10) hp = query + ((long long)(b * 10 + q) * 2) * Dc;
    else        hp = negative + ((long long)(b * 512 + (q - 10)) * 2) * Dc;
    const float* tp = hp + Dc;
    float u[4], rr[4], nn2[4], al = 0.0f;
#pragma unroll
    for (int i = 0; i < 4; i++) {
        int o = lane + 32 * i;
        if (o < Dc) { u[i] = hp[o] - tp[o]; rr[i] = rq[o]; nn2[i] = nq[o]; }
        else        { u[i] = 0.0f; rr[i] = 0.0f; nn2[i] = 0.0f; }
        al += u[i] * nn2[i];
    }
    al = warpred(al);
    float s = 0.0f;
#pragma unroll
    for (int i = 0; i < 4; i++) {
        float d = u[i] + rr[i] - al * nn2[i];
        s += d * d;
    }
    s = warpred(s);
    if (lane == 0) {
        float sc = -sqrtf(s);
        if (q < 10) out[b * 10 + q] = sc;
        else        out[2560 + (long long)b * 512 + (q - 10)] = sc;
    }
}

// ============ host launcher ================================================
extern "C" void kernel_launch(void* const* d_in, const int* in_sizes, int n_in,
                              void* d_out, int out_size)
{
    const float* support  = (const float*)d_in[0];
    const float* sneg     = (const float*)d_in[1];
    const float* query    = (const float*)d_in[2];
    const float* negative = (const float*)d_in[3];
    const float* normv    = (const float*)d_in[4];
    const int*   leftc    = (const int*)d_in[5];
    const int*   rightc   = (const int*)d_in[6];
    const float* emb      = (const float*)d_in[7];
    const float* gcn_w    = (const float*)d_in[8];
    const float* gcn_wb   = (const float*)d_in[9];
    const float* gcn_b    = (const float*)d_in[10];
    const float* attn_w   = (const float*)d_in[11];
    const float* attn_wb  = (const float*)d_in[12];
    const float* gate_w   = (const float*)d_in[13];
    const float* gate_wb  = (const float*)d_in[14];
    const float* gate_b   = (const float*)d_in[15];
    const float* Wih0     = (const float*)d_in[16];
    const float* Whh0     = (const float*)d_in[17];
    const float* bih0     = (const float*)d_in[18];
    const float* bhh0     = (const float*)d_in[19];
    const float* Wih1     = (const float*)d_in[20];
    const float* Whh1     = (const float*)d_in[21];
    const float* bih1     = (const float*)d_in[22];
    const float* bhh1     = (const float*)d_in[23];
    const float* out_w    = (const float*)d_in[24];
    const float* out_b    = (const float*)d_in[25];
    float* out = (float*)d_out;

    float *P, *W2, *XW0v, *XW1v, *Y1, *HA, *HB, *Cst, *Whh0i, *Whh1i, *BS0, *BS1;
    __nv_bfloat16 *Xb, *Y0b, *Wih0b, *Wih1b;
    cudaGetSymbolAddress((void**)&P,     d_P);
    cudaGetSymbolAddress((void**)&W2,    d_W2);
    cudaGetSymbolAddress((void**)&Xb,    d_Xb);
    cudaGetSymbolAddress((void**)&Y0b,   d_y0b);
    cudaGetSymbolAddress((void**)&Wih0b, d_Wih0b);
    cudaGetSymbolAddress((void**)&Wih1b, d_Wih1b);
    cudaGetSymbolAddress((void**)&XW0v,  d_XW0);
    cudaGetSymbolAddress((void**)&XW1v,  d_XW1);
    cudaGetSymbolAddress((void**)&Y1,    d_y1);
    cudaGetSymbolAddress((void**)&HA,    d_hA);
    cudaGetSymbolAddress((void**)&HB,    d_hB);
    cudaGetSymbolAddress((void**)&Cst,   d_cst);
    cudaGetSymbolAddress((void**)&Whh0i, d_Whh0i);
    cudaGetSymbolAddress((void**)&Whh1i, d_Whh1i);
    cudaGetSymbolAddress((void**)&BS0,   d_bs0);
    cudaGetSymbolAddress((void**)&BS1,   d_bs1);

    const int prepN = 27200 + 2 * (2 * Bc * HP) + 1280 * 40 + 1280 * 52;
    prep_small<<<(prepN + 255) / 256, 256>>>(gcn_w, bih0, bhh0, bih1, bhh1);
    const int ihbN = 2 * NPAD * K0P + 2 * NPAD * K1P;
    prep_ihb<<<(ihbN + 255) / 256, 256>>>(Wih0, Wih1);
    prep_hh<<<(2 * 2 * NP * HP + 255) / 256, 256>>>(Whh0, Whh1);

    // P = emb @ W2^T (fp32 path)
    {
        dim3 g(2, (NSYMc + 1 + 127) / 128, 1);
        sgemm_nt<128, 128, 16, 8, 8, true><<<g, 256>>>(NSYMc + 1, 200, 100, 7,
            emb, 100, 0, W2, 100, 0, P, 200, 0);
    }
    cudaFuncSetAttribute(encoder_kernel, cudaFuncAttributeMaxDynamicSharedMemorySize,
                         Mc * Dc * (int)sizeof(float));
    encoder_kernel<<<FEWc * 2 * Bc, 256, Mc * Dc * sizeof(float)>>>(
        leftc, rightc, emb, gcn_wb, gcn_b, attn_w, attn_wb, gate_w, gate_wb, gate_b);

    const int HG_SMEM = 3 * 2 * 128 * 72 * (int)sizeof(__nv_bfloat16);  // 110592
    cudaFuncSetAttribute(hgemm_nt, cudaFuncAttributeMaxDynamicSharedMemorySize, HG_SMEM);

    dim3 ghg(NPAD / 128, 1280 / 128, 2);
    dim3 grec(29, 4, 2);

    // layer 0: XW0 = X' @ Wih0'^T  (bf16 tensor cores, BK=64, 3-stage)
    hgemm_nt<<<ghg, 256, HG_SMEM>>>(K0P / 64, Xb, K0P, 0,
                                    Wih0b, K0P, (long long)NPAD * K0P, XW0v, XWS, NPAD);
    lstm_step0<<<900, 256>>>(XW0v, BS0, HA, Cst, nullptr, Y0b);
    float* hbuf[2] = {HA, HB};
    for (int s = 1; s < 5; s++)
        lstm_rec<<<grec, 256>>>(hbuf[(s + 1) & 1], Whh0i, XW0v, BS0, hbuf[s & 1], Cst,
                                nullptr, Y0b, s, 0);
    // layer 1: XW1 = y0' @ Wih1'^T  (bf16 tensor cores, BK=64, 3-stage)
    hgemm_nt<<<ghg, 256, HG_SMEM>>>(K1P / 64, Y0b, K1P, 0,
                                    Wih1b, K1P, (long long)NPAD * K1P, XW1v, XWS, NPAD);
    lstm_step0<<<900, 256>>>(XW1v, BS1, HA, Cst, Y1, nullptr);
    for (int s = 1; s < 5; s++)
        lstm_rec<<<grec, 256>>>(hbuf[(s + 1) & 1], Whh1i, XW1v, BS1, hbuf[s & 1], Cst,
                                Y1, nullptr, s, 2);

    attn_kernel<<<Bc, 256>>>(out_w, out_b);
    meta_kernel<<<Bc, 32>>>(support, sneg, normv);
    score_kernel<<<dim3((522 + 7) / 8, Bc), 256>>>(query, negative, out);
}

// round 16
// speedup vs baseline: 1.0121x; 1.0121x over previous
#include <cuda_runtime.h>
#include <cuda_bf16.h>
#include <mma.h>
#include <math.h>

using namespace nvcuda;

#define Bc 256
#define FEWc 5
#define Mc 200
#define Dc 100
#define Hc 450
#define NSYMc 70000
#define HP 464
#define NP 1856
#define K0P 608
#define K1P 2720
#define NPAD 1920
#define XWS 3840

__device__ __align__(16) float d_P[(NSYMc + 1) * 200];
__device__ __align__(16) float d_W2[200 * 100];
__device__ __align__(16) __nv_bfloat16 d_Xb[1280 * K0P];
__device__ __align__(16) __nv_bfloat16 d_y0b[1280 * K1P];
__device__ __align__(16) __nv_bfloat16 d_Wih0b[2 * NPAD * K0P];
__device__ __align__(16) __nv_bfloat16 d_Wih1b[2 * NPAD * K1P];
__device__ __align__(16) float d_XW0[1280 * XWS];
__device__ __align__(16) float d_XW1[1280 * XWS];
__device__ __align__(16) float d_y1[FEWc * Bc * 900];
__device__ __align__(16) float d_hA[2 * Bc * HP];
__device__ __align__(16) float d_hB[2 * Bc * HP];
__device__ __align__(16) float d_Whh0i[2 * NP * HP];
__device__ __align__(16) float d_Whh1i[2 * NP * HP];
__device__ __align__(16) float d_bs0[2 * 1800];
__device__ __align__(16) float d_bs1[2 * 1800];
__device__ __align__(16) float d_finals[4 * Bc * Hc];
__device__ __align__(16) float d_rel[Bc * Dc];
__device__ __align__(16) float d_relq[Bc * Dc];
__device__ __align__(16) float d_normq[Bc * Dc];
__device__ unsigned d_bcnt[4];
__device__ unsigned d_bgen[4];

__device__ __forceinline__ float sigm(float x) { return 1.0f / (1.0f + expf(-x)); }
__device__ __forceinline__ float warpred(float v) {
    for (int o = 16; o > 0; o >>= 1) v += __shfl_xor_sync(0xffffffff, v, o);
    return v;
}
__device__ __forceinline__ void split_bf(float x, __nv_bfloat16& hi, __nv_bfloat16& lo) {
    hi = __float2bfloat16(x);
    lo = __float2bfloat16(x - __bfloat162float(hi));
}

// group barrier across the 29 blocks of one (mb,dir) group; all co-resident.
__device__ __forceinline__ void groupbar(int gid) {
    __syncthreads();
    __threadfence();
    if (threadIdx.x == 0) {
        unsigned gen = atomicAdd(&d_bgen[gid], 0u);
        if (atomicAdd(&d_bcnt[gid], 1u) == 28u) {
            atomicExch(&d_bcnt[gid], 0u);
            __threadfence();
            atomicAdd(&d_bgen[gid], 1u);
        } else {
            while (atomicAdd(&d_bgen[gid], 0u) == gen) __nanosleep(32);
        }
    }
    __syncthreads();
    __threadfence();
}

#define CP16(smaddr, gptr) \
    asm volatile("cp.async.cg.shared.global [%0], [%1], 16;\n" :: "r"(smaddr), "l"(gptr))
#define CP_COMMIT() asm volatile("cp.async.commit_group;\n" ::)
#define CP_WAIT0()  asm volatile("cp.async.wait_group 0;\n" ::)
#define CP_WAIT1()  asm volatile("cp.async.wait_group 1;\n" ::)

// ====== bf16 tensor-core NT GEMM, BK=32, 3-stage cp.async (R14 proven) =====
__global__ __launch_bounds__(256) void hgemm_nt(
    int T,
    const __nv_bfloat16* __restrict__ A, int lda, long long sA,
    const __nv_bfloat16* __restrict__ Bm, int ldb, long long sB,
    float* __restrict__ C, int ldc, long long sC)
{
    constexpr int LDS_ = 40;
    constexpr int STAGE = 128 * LDS_;
    extern __shared__ __nv_bfloat16 sm[];
    A  += (long long)blockIdx.z * sA;
    Bm += (long long)blockIdx.z * sB;
    C  += (long long)blockIdx.z * sC;
    const int tid = threadIdx.x;
    const int warp = tid >> 5;
    const int warpM = warp >> 2, warpN = warp & 3;
    const int m0 = blockIdx.y * 128, n0 = blockIdx.x * 128;
    const int r0 = tid >> 2, cs0 = (tid & 3) * 8;
    const int r1 = (tid + 256) >> 2, cs1 = ((tid + 256) & 3) * 8;

    auto issue = [&](int t, int buf) {
        const __nv_bfloat16* Ak = A + (long long)m0 * lda + t * 32;
        const __nv_bfloat16* Bk = Bm + (long long)n0 * ldb + t * 32;
        __nv_bfloat16* sa = sm + buf * 2 * STAGE;
        __nv_bfloat16* sb = sa + STAGE;
        CP16((unsigned)__cvta_generic_to_shared(sa + r0 * LDS_ + cs0), Ak + (long long)r0 * lda + cs0);
        CP16((unsigned)__cvta_generic_to_shared(sa + r1 * LDS_ + cs1), Ak + (long long)r1 * lda + cs1);
        CP16((unsigned)__cvta_generic_to_shared(sb + r0 * LDS_ + cs0), Bk + (long long)r0 * ldb + cs0);
        CP16((unsigned)__cvta_generic_to_shared(sb + r1 * LDS_ + cs1), Bk + (long long)r1 * ldb + cs1);
        CP_COMMIT();
    };

    wmma::fragment<wmma::accumulator, 16, 16, 16, float> acc[4][2];
#pragma unroll
    for (int i = 0; i < 4; i++)
#pragma unroll
        for (int j = 0; j < 2; j++) wmma::fill_fragment(acc[i][j], 0.0f);

    issue(0, 0);
    if (T > 1) issue(1, 1);
    int buf = 0;
    for (int t = 0; t < T; t++) {
        if (t + 1 < T) CP_WAIT1();
        else           CP_WAIT0();
        __syncthreads();
        if (t + 2 < T) {
            int nb = buf + 2; if (nb >= 3) nb -= 3;
            issue(t + 2, nb);
        }
        const __nv_bfloat16* sa = sm + buf * 2 * STAGE;
        const __nv_bfloat16* sb = sa + STAGE;
#pragma unroll
        for (int ks = 0; ks < 2; ks++) {
            wmma::fragment<wmma::matrix_b, 16, 16, 16, __nv_bfloat16, wmma::col_major> bfr[2];
#pragma unroll
            for (int j = 0; j < 2; j++)
                wmma::load_matrix_sync(bfr[j], sb + (warpN * 32 + j * 16) * LDS_ + ks * 16, LDS_);
#pragma unroll
            for (int i = 0; i < 4; i++) {
                wmma::fragment<wmma::matrix_a, 16, 16, 16, __nv_bfloat16, wmma::row_major> afr;
                wmma::load_matrix_sync(afr, sa + (warpM * 64 + i * 16) * LDS_ + ks * 16, LDS_);
#pragma unroll
                for (int j = 0; j < 2; j++)
                    wmma::mma_sync(acc[i][j], afr, bfr[j], acc[i][j]);
            }
        }
        if (++buf == 3) buf = 0;
    }
#pragma unroll
    for (int i = 0; i < 4; i++)
#pragma unroll
        for (int j = 0; j < 2; j++)
            wmma::store_matrix_sync(
                C + (long long)(m0 + warpM * 64 + i * 16) * ldc + n0 + warpN * 32 + j * 16,
                acc[i][j], ldc, wmma::mem_row_major);
}

// ====== fp32 NT SGEMM (proven) — P only ====================================
template <int BM, int BN, int BK, int TM, int TN, bool GUARD>
__global__ __launch_bounds__(256, 2) void sgemm_nt(
    int M, int N, int K, int T,
    const float* __restrict__ A, int lda, long long sA,
    const float* __restrict__ Bm, int ldb, long long sB,
    float* __restrict__ C, int ldc, long long sC)
{
    constexpr int TX = BN / TN, TY = BM / TM;
    static_assert(TX * TY == 256, "");
    constexpr int KV = BK / 4;
    constexpr int NVA = BM * BK / 1024, NVB = BN * BK / 1024;
    __shared__ float As[BK][BM + 4];
    __shared__ float Bs[BK][BN + 4];
    A  += (long long)blockIdx.z * sA;
    Bm += (long long)blockIdx.z * sB;
    C  += (long long)blockIdx.z * sC;
    const int tid = threadIdx.x, tx = tid % TX, ty = tid / TX;
    const int m0 = blockIdx.y * BM, n0 = blockIdx.x * BN;
    const float4 z4 = make_float4(0.f, 0.f, 0.f, 0.f);

    float4 aR[NVA], bR[NVB];
#pragma unroll
    for (int v = 0; v < NVA; v++) {
        int idx = tid + v * 256, r = idx / KV, kv = idx % KV;
        int gm = m0 + r, gk = kv * 4;
        aR[v] = (!GUARD || (gm < M && gk < K)) ? *(const float4*)(A + (long long)gm * lda + gk) : z4;
    }
#pragma unroll
    for (int v = 0; v < NVB; v++) {
        int idx = tid + v * 256, r = idx / KV, kv = idx % KV;
        int gn = n0 + r, gk = kv * 4;
        bR[v] = (!GUARD || (gn < N && gk < K)) ? *(const float4*)(Bm + (long long)gn * ldb + gk) : z4;
    }

    unsigned long long acc2[TM][TN / 2];
#pragma unroll
    for (int i = 0; i < TM; i++)
#pragma unroll
        for (int j = 0; j < TN / 2; j++) acc2[i][j] = 0ull;

    for (int t = 0; t < T; t++) {
#pragma unroll
        for (int v = 0; v < NVA; v++) {
            int idx = tid + v * 256, r = idx / KV, kv = idx % KV;
            As[kv * 4 + 0][r] = aR[v].x; As[kv * 4 + 1][r] = aR[v].y;
            As[kv * 4 + 2][r] = aR[v].z; As[kv * 4 + 3][r] = aR[v].w;
        }
#pragma unroll
        for (int v = 0; v < NVB; v++) {
            int idx = tid + v * 256, r = idx / KV, kv = idx % KV;
            Bs[kv * 4 + 0][r] = bR[v].x; Bs[kv * 4 + 1][r] = bR[v].y;
            Bs[kv * 4 + 2][r] = bR[v].z; Bs[kv * 4 + 3][r] = bR[v].w;
        }
        __syncthreads();
        if (t + 1 < T) {
            int k0 = (t + 1) * BK;
#pragma unroll
            for (int v = 0; v < NVA; v++) {
                int idx = tid + v * 256, r = idx / KV, kv = idx % KV;
                int gm = m0 + r, gk = k0 + kv * 4;
                aR[v] = (!GUARD || (gm < M && gk < K)) ? *(const float4*)(A + (long long)gm * lda + gk) : z4;
            }
#pragma unroll
            for (int v = 0; v < NVB; v++) {
                int idx = tid + v * 256, r = idx / KV, kv = idx % KV;
                int gn = n0 + r, gk = k0 + kv * 4;
                bR[v] = (!GUARD || (gn < N && gk < K)) ? *(const float4*)(Bm + (long long)gn * ldb + gk) : z4;
            }
        }
#pragma unroll
        for (int kk = 0; kk < BK; kk++) {
            float4 raV[TM / 4];
#pragma unroll
            for (int i = 0; i < TM / 4; i++)
                raV[i] = *(const float4*)&As[kk][ty * TM + 4 * i];
            const float* ra = (const float*)raV;
            float4 rbV[TN / 4];
#pragma unroll
            for (int j = 0; j < TN / 4; j++)
                rbV[j] = *(const float4*)&Bs[kk][tx * TN + 4 * j];
            const unsigned long long* rb = (const unsigned long long*)rbV;
#pragma unroll
            for (int i = 0; i < TM; i++) {
                unsigned long long a2;
                unsigned au = __float_as_uint(ra[i]);
                asm("mov.b64 %0,{%1,%1};" : "=l"(a2) : "r"(au));
#pragma unroll
                for (int j = 0; j < TN / 2; j++)
                    asm("fma.rn.f32x2 %0,%1,%2,%3;"
                        : "=l"(acc2[i][j]) : "l"(a2), "l"(rb[j]), "l"(acc2[i][j]));
            }
        }
        __syncthreads();
    }
#pragma unroll
    for (int i = 0; i < TM; i++) {
        int m = m0 + ty * TM + i;
        if (m >= M) continue;
#pragma unroll
        for (int j = 0; j < TN / 2; j++) {
            union { unsigned long long u; float f[2]; } cv;
            cv.u = acc2[i][j];
            int n = n0 + tx * TN + 2 * j;
            if (n + 1 < N) *(float2*)(C + (long long)m * ldc + n) = make_float2(cv.f[0], cv.f[1]);
            else if (n < N) C[(long long)m * ldc + n] = cv.f[0];
        }
    }
}

// ====== persistent LSTM layer: all 5 steps in one kernel ====================
// grid (29, 2, 2): nb gate-col block (64 cols), mb batch block (128 rows), dir.
// c state in registers; h double-buffered via hA/hB; group barrier per step.
__global__ __launch_bounds__(256) void lstm_layer(
    const float* __restrict__ Whh, const float* __restrict__ XW,
    const float* __restrict__ bs,
    float* __restrict__ hA, float* __restrict__ hB,
    float* __restrict__ yf, __nv_bfloat16* __restrict__ ybf,
    int finalsBase)
{
    __shared__ float As[16][132];
    __shared__ float Bs[16][68];
    const int nb = blockIdx.x, mb = blockIdx.y, dir = blockIdx.z;
    const int gid = mb * 2 + dir;
    const int tid = threadIdx.x, tx = tid & 15, ty = tid >> 4;
    const int m0 = mb * 128, n0 = nb * 64;
    const float* Bm = Whh + (long long)dir * NP * HP;
    const int jj = (n0 >> 2) + tx;
    const bool jok = (jj < Hc);
    float4 bsv = make_float4(0.f, 0.f, 0.f, 0.f);
    if (jok) bsv = *(const float4*)(bs + dir * 1800 + 4 * jj);

    float creg[8];

    // ---- step 0 (no recurrent term) ----
    {
        const int t0 = dir ? 4 : 0;
        if (jok) {
#pragma unroll
            for (int i = 0; i < 8; i++) {
                int b = m0 + ty * 8 + i;
                const float4 xwv = *(const float4*)(XW + ((long long)(t0 * Bc + b)) * XWS + dir * NPAD + 4 * jj);
                float gi = xwv.x + bsv.x, gg = xwv.z + bsv.z, go = xwv.w + bsv.w;
                float cn = sigm(gi) * tanhf(gg);
                float hn = sigm(go) * tanhf(cn);
                creg[i] = cn;
                hA[((long long)dir * Bc + b) * HP + jj] = hn;
                if (ybf) {
                    __nv_bfloat16 hi, lo;
                    split_bf(hn, hi, lo);
                    long long base = ((long long)(t0 * Bc + b)) * K1P + 3 * (dir * Hc + jj);
                    ybf[base] = hi; ybf[base + 1] = lo; ybf[base + 2] = hi;
                } else {
                    yf[((long long)(t0 * Bc + b)) * 900 + dir * Hc + jj] = hn;
                }
            }
        }
    }

    const float* hin = hA;
    float* hout = hB;
    const int r = tid >> 2, kv = tid & 3;

    for (int step = 1; step < 5; step++) {
        groupbar(gid);   // previous step's h writes complete & visible

        const float* A = hin + (long long)dir * Bc * HP;
        unsigned long long acc2[8][2];
#pragma unroll
        for (int i = 0; i < 8; i++) { acc2[i][0] = 0ull; acc2[i][1] = 0ull; }

        float4 aR0 = *(const float4*)(A + (long long)(m0 + r) * HP + kv * 4);
        float4 aR1 = *(const float4*)(A + (long long)(m0 + 64 + r) * HP + kv * 4);
        float4 bR  = *(const float4*)(Bm + (long long)(n0 + r) * HP + kv * 4);

        for (int t = 0; t < HP / 16; t++) {
            As[kv * 4 + 0][r] = aR0.x; As[kv * 4 + 1][r] = aR0.y;
            As[kv * 4 + 2][r] = aR0.z; As[kv * 4 + 3][r] = aR0.w;
            As[kv * 4 + 0][64 + r] = aR1.x; As[kv * 4 + 1][64 + r] = aR1.y;
            As[kv * 4 + 2][64 + r] = aR1.z; As[kv * 4 + 3][64 + r] = aR1.w;
            Bs[kv * 4 + 0][r] = bR.x; Bs[kv * 4 + 1][r] = bR.y;
            Bs[kv * 4 + 2][r] = bR.z; Bs[kv * 4 + 3][r] = bR.w;
            __syncthreads();
            if (t + 1 < HP / 16) {
                int gk = (t + 1) * 16 + kv * 4;
                aR0 = *(const float4*)(A + (long long)(m0 + r) * HP + gk);
                aR1 = *(const float4*)(A + (long long)(m0 + 64 + r) * HP + gk);
                bR  = *(const float4*)(Bm + (long long)(n0 + r) * HP + gk);
            }
#pragma unroll
            for (int kk = 0; kk < 16; kk++) {
                float4 raV0 = *(const float4*)&As[kk][ty * 8];
                float4 raV1 = *(const float4*)&As[kk][ty * 8 + 4];
                const float* ra0 = (const float*)&raV0;
                const float* ra1 = (const float*)&raV1;
                float4 rbV = *(const float4*)&Bs[kk][tx * 4];
                const unsigned long long* rb = (const unsigned long long*)&rbV;
#pragma unroll
                for (int i = 0; i < 4; i++) {
                    unsigned long long a2;
                    unsigned au = __float_as_uint(ra0[i]);
                    asm("mov.b64 %0,{%1,%1};" : "=l"(a2) : "r"(au));
                    asm("fma.rn.f32x2 %0,%1,%2,%3;" : "=l"(acc2[i][0]) : "l"(a2), "l"(rb[0]), "l"(acc2[i][0]));
                    asm("fma.rn.f32x2 %0,%1,%2,%3;" : "=l"(acc2[i][1]) : "l"(a2), "l"(rb[1]), "l"(acc2[i][1]));
                }
#pragma unroll
                for (int i = 0; i < 4; i++) {
                    unsigned long long a2;
                    unsigned au = __float_as_uint(ra1[i]);
                    asm("mov.b64 %0,{%1,%1};" : "=l"(a2) : "r"(au));
                    asm("fma.rn.f32x2 %0,%1,%2,%3;" : "=l"(acc2[4 + i][0]) : "l"(a2), "l"(rb[0]), "l"(acc2[4 + i][0]));
                    asm("fma.rn.f32x2 %0,%1,%2,%3;" : "=l"(acc2[4 + i][1]) : "l"(a2), "l"(rb[1]), "l"(acc2[4 + i][1]));
                }
            }
            __syncthreads();
        }

        // epilogue
        const int tstep = dir ? (4 - step) : step;
        if (jok) {
#pragma unroll
            for (int i = 0; i < 8; i++) {
                int b = m0 + ((i < 4) ? (ty * 4 + i) : (64 + ty * 4 + (i - 4)));
                // NOTE: row mapping must match GEMM: acc2[i] i<4 -> rows ty*4..? 
                // We used ra0 = As[kk][ty*8 .. ty*8+3] and ra1 = As[kk][ty*8+4..7]:
                // rows m0 + ty*8 + i for i<4, m0 + ty*8 + 4 + (i-4) for i>=4.
                b = m0 + ty * 8 + i;
                union { unsigned long long u; float f[2]; } c0, c1;
                c0.u = acc2[i][0]; c1.u = acc2[i][1];
                const float4 xwv = *(const float4*)(XW + ((long long)(tstep * Bc + b)) * XWS + dir * NPAD + 4 * jj);
                float gi = c0.f[0] + xwv.x + bsv.x;
                float gf = c0.f[1] + xwv.y + bsv.y;
                float gg = c1.f[0] + xwv.z + bsv.z;
                float go = c1.f[1] + xwv.w + bsv.w;
                float cn = sigm(gf) * creg[i] + sigm(gi) * tanhf(gg);
                float hn = sigm(go) * tanhf(cn);
                creg[i] = cn;
                hout[((long long)dir * Bc + b) * HP + jj] = hn;
                if (ybf) {
                    __nv_bfloat16 hi, lo;
                    split_bf(hn, hi, lo);
                    long long base = ((long long)(tstep * Bc + b)) * K1P + 3 * (dir * Hc + jj);
                    ybf[base] = hi; ybf[base + 1] = lo; ybf[base + 2] = hi;
                } else {
                    yf[((long long)(tstep * Bc + b)) * 900 + dir * Hc + jj] = hn;
                }
                if (step == 4)
                    d_finals[((long long)(finalsBase + dir) * Bc + b) * Hc + jj] = hn;
            }
        }
        const float* tmp = hin; hin = hout; hout = (float*)tmp;
    }
}

// ============ prep kernels =================================================
__global__ void prep_small(const float* __restrict__ gcn_w,
                           const float* __restrict__ bih0, const float* __restrict__ bhh0,
                           const float* __restrict__ bih1, const float* __restrict__ bhh1)
{
    int i = blockIdx.x * blockDim.x + threadIdx.x;
    const int HZ = 2 * Bc * HP;
    if (i < 20000) {
        int op = i / 100, k = i - op * 100;
        d_W2[op * 100 + k] = gcn_w[(op % 100) * 200 + (op / 100) * 100 + k];
    } else if (i < 23600) {
        int r = i - 20000, dir = r / 1800, q = r - dir * 1800;
        int j = q >> 2, g = q & 3, s = dir * 1800 + g * 450 + j;
        d_bs0[dir * 1800 + q] = bih0[s] + bhh0[s];
    } else if (i < 27200) {
        int r = i - 23600, dir = r / 1800, q = r - dir * 1800;
        int j = q >> 2, g = q & 3, s = dir * 1800 + g * 450 + j;
        d_bs1[dir * 1800 + q] = bih1[s] + bhh1[s];
    } else if (i < 27200 + HZ) {
        d_hA[i - 27200] = 0.0f;
    } else if (i < 27200 + 2 * HZ) {
        d_hB[i - 27200 - HZ] = 0.0f;
    } else if (i < 27200 + 2 * HZ + 1280 * 8) {
        int i2 = i - 27200 - 2 * HZ;
        int row = i2 / 8, cc = 600 + (i2 % 8);
        d_Xb[(long long)row * K0P + cc] = __float2bfloat16(0.0f);
    } else if (i < 27200 + 2 * HZ + 1280 * 8 + 1280 * 20) {
        int i2 = i - 27200 - 2 * HZ - 1280 * 8;
        int row = i2 / 20, cc = 2700 + (i2 % 20);
        d_y0b[(long long)row * K1P + cc] = __float2bfloat16(0.0f);
    }
}

__global__ void prep_ihb(const float* __restrict__ Wih0, const float* __restrict__ Wih1)
{
    const int L0SZ = 2 * NPAD * K0P;
    int i = blockIdx.x * blockDim.x + threadIdx.x;
    if (i < L0SZ) {
        int dir = i / (NPAD * K0P), rem = i - dir * (NPAD * K0P);
        int q = rem / K0P, cc = rem - q * K0P;
        __nv_bfloat16 outv = __float2bfloat16(0.0f);
        if (q < 1800 && cc < 600) {
            int k = cc / 3, p = cc - 3 * k;
            int j = q >> 2, g = q & 3;
            float w = Wih0[dir * 360000 + (g * 450 + j) * 200 + k];
            __nv_bfloat16 hi, lo;
            split_bf(w, hi, lo);
            outv = (p == 2) ? lo : hi;
        }
        d_Wih0b[i] = outv;
    } else if (i < L0SZ + 2 * NPAD * K1P) {
        int i2 = i - L0SZ;
        int dir = i2 / (NPAD * K1P), rem = i2 - dir * (NPAD * K1P);
        int q = rem / K1P, cc = rem - q * K1P;
        __nv_bfloat16 outv = __float2bfloat16(0.0f);
        if (q < 1800 && cc < 2700) {
            int k = cc / 3, p = cc - 3 * k;
            int j = q >> 2, g = q & 3;
            float w = Wih1[dir * 1620000 + (g * 450 + j) * 900 + k];
            __nv_bfloat16 hi, lo;
            split_bf(w, hi, lo);
            outv = (p == 2) ? lo : hi;
        }
        d_Wih1b[i2] = outv;
    }
}

__global__ void prep_hh(const float* __restrict__ Whh0, const float* __restrict__ Whh1)
{
    int i = blockIdx.x * blockDim.x + threadIdx.x;
    const int PER = 2 * NP * HP;
    if (i >= 2 * PER) return;
    int layer = i / PER, i2 = i - layer * PER;
    int dir = i2 / (NP * HP), rem = i2 - dir * (NP * HP);
    int r = rem / HP, k = rem - r * HP;
    float v = 0.0f;
    if (r < 1800 && k < 450) {
        int j = r >> 2, g = r & 3;
        const float* src = layer ? Whh1 : Whh0;
        v = src[dir * 810000 + (g * 450 + j) * 450 + k];
    }
    (layer ? d_Whh1i : d_Whh0i)[i2] = v;
}

// ============ neighbor encoder (1 block per row) ===========================
__global__ __launch_bounds__(256) void encoder_kernel(
    const int* __restrict__ lc, const int* __restrict__ rc,
    const float* __restrict__ emb,
    const float* __restrict__ gcn_wb, const float* __restrict__ gcn_b,
    const float* __restrict__ attn_w, const float* __restrict__ attn_wb,
    const float* __restrict__ gate_w, const float* __restrict__ gate_wb,
    const float* __restrict__ gate_b)
{
    extern __shared__ __align__(16) float outbuf[];
    __shared__ float logits[Mc], wts[Mc], bias[Dc], aw[Dc], gw[Dc], oattn[Dc], red[256], gsc;
    const int n = blockIdx.x;
    const int f = n / (2 * Bc);
    const int rem = n - f * 2 * Bc;
    const int s = rem / Bc, bb = rem - (rem / Bc) * Bc;
    const int* conn = (s == 0 ? lc : rc) + ((long long)(f * Bc + bb) * Mc) * 3;
    const int tid = threadIdx.x;
    if (tid < Dc) { bias[tid] = gcn_wb[tid] + gcn_b[tid]; aw[tid] = attn_w[tid]; gw[tid] = gate_w[tid]; }
    __syncthreads();
    const float awb = attn_wb[0];

    for (int m = tid; m < Mc; m += 256) {
        int i1 = conn[m * 3 + 1], i2 = conn[m * 3 + 2];
        const float4* p1 = (const float4*)(d_P + (long long)i1 * 200);
        const float4* p2 = (const float4*)(d_P + (long long)i2 * 200 + 100);
        float4* orow = (float4*)(outbuf + m * Dc);
        float lg = 0.0f;
#pragma unroll 25
        for (int q = 0; q < 25; q++) {
            float4 a = p1[q], b4 = p2[q];
            float v0 = a.x + b4.x + bias[4 * q + 0];
            float v1 = a.y + b4.y + bias[4 * q + 1];
            float v2 = a.z + b4.z + bias[4 * q + 2];
            float v3 = a.w + b4.w + bias[4 * q + 3];
            v0 = v0 >= 0.f ? v0 : 0.01f * v0;
            v1 = v1 >= 0.f ? v1 : 0.01f * v1;
            v2 = v2 >= 0.f ? v2 : 0.01f * v2;
            v3 = v3 >= 0.f ? v3 : 0.01f * v3;
            float4 o; o.x = v0; o.y = v1; o.z = v2; o.w = v3;
            orow[q] = o;
            lg += v0 * aw[4 * q] + v1 * aw[4 * q + 1] + v2 * aw[4 * q + 2] + v3 * aw[4 * q + 3];
        }
        logits[m] = lg + awb;
    }
    __syncthreads();

    float lm = -1e30f;
    for (int m = tid; m < Mc; m += 256) lm = fmaxf(lm, logits[m]);
    red[tid] = lm; __syncthreads();
    for (int st = 128; st > 0; st >>= 1) { if (tid < st) red[tid] = fmaxf(red[tid], red[tid + st]); __syncthreads(); }
    float mx = red[0]; __syncthreads();
    float ls = 0.0f;
    for (int m = tid; m < Mc; m += 256) { float e = expf(logits[m] - mx); wts[m] = e; ls += e; }
    red[tid] = ls; __syncthreads();
    for (int st = 128; st > 0; st >>= 1) { if (tid < st) red[tid] += red[tid + st]; __syncthreads(); }
    float inv = 1.0f / red[0]; __syncthreads();
    for (int m = tid; m < Mc; m += 256) wts[m] *= inv;
    __syncthreads();

    for (int o = tid; o < Dc; o += 256) {
        float acc = 0.0f;
        for (int m = 0; m < Mc; m++) acc += outbuf[m * Dc + o] * wts[m];
        oattn[o] = acc;
    }
    __syncthreads();

    float gd = 0.0f;
    for (int o = tid; o < Dc; o += 256) gd += oattn[o] * gw[o];
    red[tid] = gd; __syncthreads();
    for (int st = 128; st > 0; st >>= 1) { if (tid < st) red[tid] += red[tid + st]; __syncthreads(); }
    if (tid == 0) gsc = sigm(red[0] + gate_wb[0] + gate_b[0]);
    __syncthreads();
    float g = gsc;
    int self_idx = conn[0];
    const float* se = emb + (long long)self_idx * Dc;
    for (int o = tid; o < Dc; o += 256) {
        float v = oattn[o] * g + se[o] * (1.0f - g);
        __nv_bfloat16 hi, lo;
        split_bf(v, hi, lo);
        long long base = ((long long)(f * Bc + bb)) * K0P + 3 * (s * Dc + o);
        d_Xb[base] = hi; d_Xb[base + 1] = lo; d_Xb[base + 2] = hi;
    }
}

// ============ attention over LSTM output + rel projection ==================
__global__ __launch_bounds__(256) void attn_kernel(const float* __restrict__ out_w,
                                                   const float* __restrict__ out_b)
{
    __shared__ float O[FEWc * 900];
    __shared__ float Hs[1800], ctx[1800], lg[10], awt[10];
    const int b = blockIdx.x, tid = threadIdx.x;
    for (int i = tid; i < FEWc * 900; i += 256) {
        int t = i / 900, h2 = i - t * 900;
        O[i] = d_y1[((long long)t * Bc + b) * 900 + h2];
    }
    for (int i = tid; i < 1800; i += 256) Hs[i] = d_finals[(long long)b * 1800 + i];
    if (tid < 10) lg[tid] = 0.0f;
    __syncthreads();

    float part[10];
#pragma unroll
    for (int q = 0; q < 10; q++) part[q] = 0.0f;
    for (int h2 = tid; h2 < 900; h2 += 256) {
        float hl0 = Hs[2 * h2], hl1 = Hs[2 * h2 + 1];
#pragma unroll
        for (int t = 0; t < 5; t++) {
            float ov = O[t * 900 + h2];
            part[2 * t]     += ov * hl0;
            part[2 * t + 1] += ov * hl1;
        }
    }
#pragma unroll
    for (int q = 0; q < 10; q++) {
        float v = warpred(part[q]);
        if ((tid & 31) == 0) atomicAdd(&lg[q], v);
    }
    __syncthreads();
    if (tid < 2) {
        int l = tid;
        float mxv = -1e30f;
        for (int t = 0; t < 5; t++) mxv = fmaxf(mxv, lg[t * 2 + l]);
        float sm = 0.0f, e[5];
        for (int t = 0; t < 5; t++) { e[t] = expf(lg[t * 2 + l] - mxv); sm += e[t]; }
        for (int t = 0; t < 5; t++) awt[t * 2 + l] = e[t] / sm;
    }
    __syncthreads();
    for (int i = tid; i < 1800; i += 256) {
        int h2 = i >> 1, l = i & 1;
        float acc = 0.0f;
#pragma unroll
        for (int t = 0; t < 5; t++) acc += O[t * 900 + h2] * awt[t * 2 + l];
        ctx[i] = acc;
    }
    __syncthreads();
    int w = tid >> 5, lane = tid & 31;
    for (int o = w; o < Dc; o += 8) {
        float acc = 0.0f;
        for (int k = lane; k < 1800; k += 32) acc += ctx[k] * out_w[(long long)o * 1800 + k];
        acc = warpred(acc);
        if (lane == 0) d_rel[(long long)b * Dc + o] = acc + out_b[o];
    }
}

// ============ meta gradient ================================================
__global__ void meta_kernel(const float* __restrict__ support, const float* __restrict__ sneg,
                            const float* __restrict__ normv)
{
    int b = blockIdx.x, lane = threadIdx.x;
    float r4[4], n4[4], g4[4] = {0, 0, 0, 0};
#pragma unroll
    for (int i = 0; i < 4; i++) {
        int o = lane + 32 * i;
        r4[i] = (o < Dc) ? d_rel[b * Dc + o] : 0.0f;
        n4[i] = (o < Dc) ? normv[(long long)b * Dc + o] : 0.0f;
    }
    for (int k = 0; k < 5; k++) {
        const float* hp = support + ((long long)(b * 5 + k) * 2) * Dc;
        const float* tp = hp + Dc;
        const float* hn = sneg + ((long long)(b * 5 + k) * 2) * Dc;
        const float* tn = hn + Dc;
        float up[4], un[4], ap = 0.0f, an = 0.0f;
#pragma unroll
        for (int i = 0; i < 4; i++) {
            int o = lane + 32 * i;
            up[i] = (o < Dc) ? hp[o] - tp[o] : 0.0f;
            un[i] = (o < Dc) ? hn[o] - tn[o] : 0.0f;
            ap += up[i] * n4[i];
            an += un[i] * n4[i];
        }
        ap = warpred(ap); an = warpred(an);
        float dp4[4], dn4[4], sp = 0.0f, sn = 0.0f;
#pragma unroll
        for (int i = 0; i < 4; i++) {
            dp4[i] = up[i] + r4[i] - ap * n4[i];
            dn4[i] = un[i] + r4[i] - an * n4[i];
            sp += dp4[i] * dp4[i];
            sn += dn4[i] * dn4[i];
        }
        sp = warpred(sp); sn = warpred(sn);
        float Dp = sqrtf(sp), Dn = sqrtf(sn);
        if (1.0f + Dp - Dn > 0.0f) {
            float ip = 1.0f / Dp, inn = 1.0f / Dn;
#pragma unroll
            for (int i = 0; i < 4; i++) g4[i] += dp4[i] * ip - dn4[i] * inn;
        }
    }
#pragma unroll
    for (int i = 0; i < 4; i++) {
        int o = lane + 32 * i;
        if (o < Dc) {
            float g = g4[i] * (1.0f / 1280.0f);
            d_relq[b * Dc + o]  = r4[i] - 5.0f * g;
            d_normq[b * Dc + o] = n4[i] - 5.0f * g;
        }
    }
}

// ============ final scoring ================================================
__global__ __launch_bounds__(256) void score_kernel(const float* __restrict__ query,
                                                    const float* __restrict__ negative,
                                                    float* __restrict__ out)
{
    __shared__ float rq[Dc], nq[Dc];
    int b = blockIdx.y, tid = threadIdx.x;
    if (tid < Dc) { rq[tid] = d_relq[b * Dc + tid]; nq[tid] = d_normq[b * Dc + tid]; }
    __syncthreads();
    int w = tid >> 5, lane = tid & 31;
    int q = blockIdx.x * 8 + w;
    if (q >= 522) return;
    const float* hp;
    if (q < 10) hp = query + ((long long)(b * 10 + q) * 2) * Dc;
    else        hp = negative + ((long long)(b * 512 + (q - 10)) * 2) * Dc;
    const float* tp = hp + Dc;
    float u[4], rr[4], nn2[4], al = 0.0f;
#pragma unroll
    for (int i = 0; i < 4; i++) {
        int o = lane + 32 * i;
        if (o < Dc) { u[i] = hp[o] - tp[o]; rr[i] = rq[o]; nn2[i] = nq[o]; }
        else        { u[i] = 0.0f; rr[i] = 0.0f; nn2[i] = 0.0f; }
        al += u[i] * nn2[i];
    }
    al = warpred(al);
    float s = 0.0f;
#pragma unroll
    for (int i = 0; i < 4; i++) {
        float d = u[i] + rr[i] - al * nn2[i];
        s += d * d;
    }
    s = warpred(s);
    if (lane == 0) {
        float sc = -sqrtf(s);
        if (q < 10) out[b * 10 + q] = sc;
        else        out[2560 + (long long)b * 512 + (q - 10)] = sc;
    }
}

// ============ host launcher ================================================
extern "C" void kernel_launch(void* const* d_in, const int* in_sizes, int n_in,
                              void* d_out, int out_size)
{
    const float* support  = (const float*)d_in[0];
    const float* sneg     = (const float*)d_in[1];
    const float* query    = (const float*)d_in[2];
    const float* negative = (const float*)d_in[3];
    const float* normv    = (const float*)d_in[4];
    const int*   leftc    = (const int*)d_in[5];
    const int*   rightc   = (const int*)d_in[6];
    const float* emb      = (const float*)d_in[7];
    const float* gcn_w    = (const float*)d_in[8];
    const float* gcn_wb   = (const float*)d_in[9];
    const float* gcn_b    = (const float*)d_in[10];
    const float* attn_w   = (const float*)d_in[11];
    const float* attn_wb  = (const float*)d_in[12];
    const float* gate_w   = (const float*)d_in[13];
    const float* gate_wb  = (const float*)d_in[14];
    const float* gate_b   = (const float*)d_in[15];
    const float* Wih0     = (const float*)d_in[16];
    const float* Whh0     = (const float*)d_in[17];
    const float* bih0     = (const float*)d_in[18];
    const float* bhh0     = (const float*)d_in[19];
    const float* Wih1     = (const float*)d_in[20];
    const float* Whh1     = (const float*)d_in[21];
    const float* bih1     = (const float*)d_in[22];
    const float* bhh1     = (const float*)d_in[23];
    const float* out_w    = (const float*)d_in[24];
    const float* out_b    = (const float*)d_in[25];
    float* out = (float*)d_out;

    float *P, *W2, *XW0v, *XW1v, *Y1, *HA, *HB, *Whh0i, *Whh1i, *BS0, *BS1;
    __nv_bfloat16 *Xb, *Y0b, *Wih0b, *Wih1b;
    cudaGetSymbolAddress((void**)&P,     d_P);
    cudaGetSymbolAddress((void**)&W2,    d_W2);
    cudaGetSymbolAddress((void**)&Xb,    d_Xb);
    cudaGetSymbolAddress((void**)&Y0b,   d_y0b);
    cudaGetSymbolAddress((void**)&Wih0b, d_Wih0b);
    cudaGetSymbolAddress((void**)&Wih1b, d_Wih1b);
    cudaGetSymbolAddress((void**)&XW0v,  d_XW0);
    cudaGetSymbolAddress((void**)&XW1v,  d_XW1);
    cudaGetSymbolAddress((void**)&Y1,    d_y1);
    cudaGetSymbolAddress((void**)&HA,    d_hA);
    cudaGetSymbolAddress((void**)&HB,    d_hB);
    cudaGetSymbolAddress((void**)&Whh0i, d_Whh0i);
    cudaGetSymbolAddress((void**)&Whh1i, d_Whh1i);
    cudaGetSymbolAddress((void**)&BS0,   d_bs0);
    cudaGetSymbolAddress((void**)&BS1,   d_bs1);

    const int prepN = 27200 + 2 * (2 * Bc * HP) + 1280 * 8 + 1280 * 20;
    prep_small<<<(prepN + 255) / 256, 256>>>(gcn_w, bih0, bhh0, bih1, bhh1);
    const int ihbN = 2 * NPAD * K0P + 2 * NPAD * K1P;
    prep_ihb<<<(ihbN + 255) / 256, 256>>>(Wih0, Wih1);
    prep_hh<<<(2 * 2 * NP * HP + 255) / 256, 256>>>(Whh0, Whh1);

    // P = emb @ W2^T (fp32 path)
    {
        dim3 g(2, (NSYMc + 1 + 127) / 128, 1);
        sgemm_nt<128, 128, 16, 8, 8, true><<<g, 256>>>(NSYMc + 1, 200, 100, 7,
            emb, 100, 0, W2, 100, 0, P, 200, 0);
    }
    cudaFuncSetAttribute(encoder_kernel, cudaFuncAttributeMaxDynamicSharedMemorySize,
                         Mc * Dc * (int)sizeof(float));
    encoder_kernel<<<FEWc * 2 * Bc, 256, Mc * Dc * sizeof(float)>>>(
        leftc, rightc, emb, gcn_wb, gcn_b, attn_w, attn_wb, gate_w, gate_wb, gate_b);

    const int HG_SMEM = 3 * 2 * 128 * 40 * (int)sizeof(__nv_bfloat16);  // 61440
    cudaFuncSetAttribute(hgemm_nt, cudaFuncAttributeMaxDynamicSharedMemorySize, HG_SMEM);

    dim3 ghg(NPAD / 128, 1280 / 128, 2);
    dim3 glstm(29, 2, 2);

    // layer 0
    hgemm_nt<<<ghg, 256, HG_SMEM>>>(K0P / 32, Xb, K0P, 0,
                                    Wih0b, K0P, (long long)NPAD * K0P, XW0v, XWS, NPAD);
    lstm_layer<<<glstm, 256>>>(Whh0i, XW0v, BS0, HA, HB, nullptr, Y0b, 0);
    // layer 1
    hgemm_nt<<<ghg, 256, HG_SMEM>>>(K1P / 32, Y0b, K1P, 0,
                                    Wih1b, K1P, (long long)NPAD * K1P, XW1v, XWS, NPAD);
    lstm_layer<<<glstm, 256>>>(Whh1i, XW1v, BS1, HA, HB, Y1, nullptr, 2);

    attn_kernel<<<Bc, 256>>>(out_w, out_b);
    meta_kernel<<<Bc, 32>>>(support, sneg, normv);
    score_kernel<<<dim3((522 + 7) / 8, Bc), 256>>>(query, negative, out);
}